// round 5
// baseline (speedup 1.0000x reference)
#include <cuda_runtime.h>

// InfoEnlargeEmbedding: out[b,l,:] = concat(x[b,l,:], x[b,idxs[b,0],:], x[b,idxs[b,1],:])
// B=64, L=1024, D=256, K=2.
// R5: two 96-thread groups per block (warp-aligned), 16 rows/block.
// Copy lanes: 16 independent LDG.128 front-batched, 16 streaming STG.
// Gather lanes: 2 L2-hit loads, 16 streaming STG. Deep write stream per warp.

static constexpr int B = 64;
static constexpr int L = 1024;
static constexpr int D4 = 64;               // float4 per source row
static constexpr int K = 2;
static constexpr int OUT4 = D4 * (1 + K);   // 192 float4 per output row
static constexpr int R = 16;                // rows per block
static constexpr int RG = 8;                // rows per 96-thread group
static constexpr int T = 192;

__global__ void __launch_bounds__(T)
info_enlarge_kernel(const float4* __restrict__ x,
                    const int* __restrict__ idxs,
                    float4* __restrict__ out) {
    const int row0 = blockIdx.x * R;        // base bl; R divides L so same b
    const int b    = row0 >> 10;            // / L
    const int t    = threadIdx.x;

    const int grp  = t / 96;                // 0 or 1 (warp-aligned: warps 0-2 / 3-5)
    const int s    = t - grp * 96;          // 0..95
    const int rb   = row0 + grp * RG;       // this group's 8 rows

    if (s < 32) {
        // ---- copy lanes: columns {2s, 2s+1}, 8 rows ----
        const int c0 = 2 * s;
        float4 v[2 * RG];
        #pragma unroll
        for (int u = 0; u < RG; u++) {
            const float4* p = x + (size_t)(rb + u) * D4 + c0;
            v[2 * u + 0] = p[0];
            v[2 * u + 1] = p[1];
        }
        #pragma unroll
        for (int u = 0; u < RG; u++) {
            float4* q = out + (size_t)(rb + u) * OUT4 + c0;
            __stcs(q + 0, v[2 * u + 0]);
            __stcs(q + 1, v[2 * u + 1]);
        }
    } else {
        // ---- gather lanes: columns {64+2q, 65+2q}, same value for all 8 rows ----
        const int q  = s - 32;              // 0..63
        const int k  = q >> 5;
        const int dd = (q & 31) * 2;
        const int li = __ldg(idxs + b * K + k);
        const float4* p = x + ((size_t)b * L + li) * D4 + dd;
        const float4 g0 = __ldg(p);
        const float4 g1 = __ldg(p + 1);
        const int oc = D4 + k * D4 + dd;
        #pragma unroll
        for (int u = 0; u < RG; u++) {
            float4* qo = out + (size_t)(rb + u) * OUT4 + oc;
            __stcs(qo + 0, g0);
            __stcs(qo + 1, g1);
        }
    }
}

extern "C" void kernel_launch(void* const* d_in, const int* in_sizes, int n_in,
                              void* d_out, int out_size) {
    const float4* x  = (const float4*)d_in[0];
    const int* idxs  = (const int*)d_in[1];
    float4* out      = (float4*)d_out;

    info_enlarge_kernel<<<(B * L) / R, T>>>(x, idxs, out);
}

// round 6
// speedup vs baseline: 1.3034x; 1.3034x over previous
#include <cuda_runtime.h>

// InfoEnlargeEmbedding: out[b,l,:] = concat(x[b,l,:], x[b,idxs[b,0],:], x[b,idxs[b,1],:])
// B=64, L=1024, D=256, K=2.
// R6: exact R2 structure (best: 40.3us kernel), but DEFAULT cache policy on
// all loads/stores — testing whether .cs evict-first stores were throttling
// DRAM write drain. Copy threads: 8 independent LDG.128 -> 8 STG.128.
// Gather threads: 1 L2-hit load -> 8 STG.128.

static constexpr int B = 64;
static constexpr int L = 1024;
static constexpr int D4 = 64;               // float4 per source row
static constexpr int K = 2;
static constexpr int OUT4 = D4 * (1 + K);   // 192 float4 per output row
static constexpr int R = 8;                 // rows (bl) per block

__global__ void __launch_bounds__(OUT4)
info_enlarge_kernel(const float4* __restrict__ x,
                    const int* __restrict__ idxs,
                    float4* __restrict__ out) {
    const int row0 = blockIdx.x * R;        // base bl; all R rows share b
    const int b    = row0 >> 10;            // / L
    const int c    = threadIdx.x;           // 0..191

    if (c < D4) {
        // Straight copy region: 8 independent loads, then 8 stores.
        float4 v[R];
        #pragma unroll
        for (int u = 0; u < R; u++)
            v[u] = x[(size_t)(row0 + u) * D4 + c];
        #pragma unroll
        for (int u = 0; u < R; u++)
            out[(size_t)(row0 + u) * OUT4 + c] = v[u];
    } else {
        // Gather region: same source row for all 8 output rows.
        const int kd = c - D4;
        const int k  = kd >> 6;             // / D4
        const int dd = kd & (D4 - 1);
        const int li = __ldg(idxs + b * K + k);
        const float4 v = __ldg(x + ((size_t)b * L + li) * D4 + dd);
        #pragma unroll
        for (int u = 0; u < R; u++)
            out[(size_t)(row0 + u) * OUT4 + c] = v;
    }
}

extern "C" void kernel_launch(void* const* d_in, const int* in_sizes, int n_in,
                              void* d_out, int out_size) {
    const float4* x  = (const float4*)d_in[0];
    const int* idxs  = (const int*)d_in[1];
    float4* out      = (float4*)d_out;

    info_enlarge_kernel<<<(B * L) / R, OUT4>>>(x, idxs, out);
}